// round 9
// baseline (speedup 1.0000x reference)
#include <cuda_runtime.h>
#include <cuda_bf16.h>
#include <cstdint>
#include <math.h>

// Problem constants
#define Hn    81
#define G3    243          // 3*H
#define RPAD  244
#define NPAIR 122
#define Fn    128
#define Tn    1024
#define Bn    512
#define BPC   4
#define NCTA  128          // 512/4

// =====================================================================
// Device scratch
// =====================================================================
__device__ float4 g_xg[Tn * NCTA * RPAD];   // [t][ctab][b(4)][r(244)] = 512 MB
__device__ float g_h8[Bn * 8];
__device__ unsigned g_prog[NCTA];           // produced-t count per ctab (sticky across replays: benign)

// ---------- packed f32x2 helpers ----------
static __device__ __forceinline__ unsigned long long dup2(float x) {
    unsigned long long r;
    asm("mov.b64 %0, {%1, %1};" : "=l"(r) : "f"(x));
    return r;
}
static __device__ __forceinline__ void ffma2(unsigned long long &d,
                                             unsigned long long a,
                                             unsigned long long b) {
    asm("fma.rn.f32x2 %0, %1, %2, %0;" : "+l"(d) : "l"(a), "l"(b));
}
static __device__ __forceinline__ unsigned long long addx2(unsigned long long a,
                                                           unsigned long long b) {
    unsigned long long r;
    asm("add.rn.f32x2 %0, %1, %2;" : "=l"(r) : "l"(a), "l"(b));
    return r;
}
static __device__ __forceinline__ float2 unpk(unsigned long long v) {
    float lo, hi;
    asm("mov.b64 {%0, %1}, %2;" : "=f"(lo), "=f"(hi) : "l"(v));
    return make_float2(lo, hi);
}

// ---------- fast activations ----------
static __device__ __forceinline__ float sigm(float x) {
    x = fminf(fmaxf(x, -30.f), 30.f);
    return __fdividef(1.f, 1.f + __expf(-x));
}
static __device__ __forceinline__ float tanh_f(float x) {
    x = fminf(fmaxf(x, -20.f), 20.f);
    float e = __expf(-2.f * x);
    return __fdividef(1.f - e, 1.f + e);
}

// ---------- mma helpers ----------
#define KPITCH   144                     // bytes per row (64 bf16 data + pad); 16B-mult
#define TILE_SZ  (128 * KPITCH)          // 18432
#define SM_AHI   0
#define SM_ALO   (SM_AHI + TILE_SZ)
#define SM_BHI   (SM_ALO + TILE_SZ)
#define SM_BLO   (SM_BHI + TILE_SZ)
#define SM_BS    (4 * TILE_SZ)           // 73728: bias 128 floats
#define SM_BYTES (SM_BS + 512)           // 74240 -> 2 CTAs/SM
#define CPITCH   132

static __device__ __forceinline__ uint32_t smem_u32(const void* p) {
    uint32_t a;
    asm("{ .reg .u64 t; cvta.to.shared.u64 t, %1; cvt.u32.u64 %0, t; }"
        : "=r"(a) : "l"(p));
    return a;
}
static __device__ __forceinline__ uint32_t bfpack(float a, float b) {
    uint32_t r;
    asm("cvt.rn.bf16x2.f32 %0, %1, %2;" : "=r"(r) : "f"(b), "f"(a));
    return r;
}
static __device__ __forceinline__ void cvt8(char* thi, char* tlo, int off, float4 v) {
    uint32_t h0 = bfpack(v.x, v.y);
    uint32_t h1 = bfpack(v.z, v.w);
    float fx = __uint_as_float(h0 << 16);
    float fy = __uint_as_float(h0 & 0xffff0000u);
    float fz = __uint_as_float(h1 << 16);
    float fw = __uint_as_float(h1 & 0xffff0000u);
    uint32_t l0 = bfpack(v.x - fx, v.y - fy);
    uint32_t l1 = bfpack(v.z - fz, v.w - fw);
    *(uint2*)(thi + off) = make_uint2(h0, h1);
    *(uint2*)(tlo + off) = make_uint2(l0, l1);
}
static __device__ __forceinline__ void ldx4(uint32_t* r, uint32_t addr) {
    asm volatile("ldmatrix.sync.aligned.m8n8.x4.shared.b16 {%0,%1,%2,%3}, [%4];"
                 : "=r"(r[0]), "=r"(r[1]), "=r"(r[2]), "=r"(r[3]) : "r"(addr));
}
static __device__ __forceinline__ void mma16816(float* c, const uint32_t* a,
                                                const uint32_t* b) {
    asm volatile(
        "mma.sync.aligned.m16n8k16.row.col.f32.bf16.bf16.f32 "
        "{%0,%1,%2,%3}, {%4,%5,%6,%7}, {%8,%9}, {%0,%1,%2,%3};"
        : "+f"(c[0]), "+f"(c[1]), "+f"(c[2]), "+f"(c[3])
        : "r"(a[0]), "r"(a[1]), "r"(a[2]), "r"(a[3]), "r"(b[0]), "r"(b[1]));
}
static __device__ __forceinline__ unsigned ld_acq(const unsigned* p) {
    unsigned v;
    asm volatile("ld.acquire.gpu.global.u32 %0, [%1];" : "=r"(v) : "l"(p) : "memory");
    return v;
}
static __device__ __forceinline__ void st_rel(unsigned* p, unsigned v) {
    asm volatile("st.release.gpu.global.u32 [%0], %1;" :: "l"(p), "r"(v) : "memory");
}

// =====================================================================
// GEMM producer role: XG(ctab) for all t, chunk-published.
// =====================================================================
static __device__ void gemm_role(char* sm, int ctab,
                                 const float* __restrict__ x,
                                 const float* __restrict__ W_ih,
                                 const float* __restrict__ b_ih) {
    const uint32_t smb = smem_u32(sm);
    float* bsm = (float*)(sm + SM_BS);
    const int tid  = threadIdx.x;
    const int lane = tid & 31;
    const int w    = tid >> 5;
    const int b0   = ctab * BPC;
    const long sbt = (long)Tn * Fn;

    const int wm = (w & 3) * 32;
    const int wn = (w >> 2) * 64;

    int aoff[2], boff[2][2];
    {
        int lr = lane & 15, lk8 = (lane >> 4) * 8;
        aoff[0] = (wm + lr) * KPITCH + lk8 * 2;
        aoff[1] = (wm + 16 + lr) * KPITCH + lk8 * 2;
        int sel = lane >> 3;
        int kk = (sel & 1) * 8;
        #pragma unroll
        for (int nh = 0; nh < 2; nh++) {
            int nrow = wn + nh * 32 + (lane & 7) + (sel >> 1) * 8;
            boff[nh][0] = nrow * KPITCH + kk * 2;
            boff[nh][1] = (nrow + 16) * KPITCH + kk * 2;
        }
    }
    const int r2 = tid >> 1, kh = tid & 1;
    const int bcol = r2 & 3, tcol = r2 >> 2;

    for (int tc = 0; tc < 32; tc++) {
        const int t0 = tc * 32;
        #pragma unroll 1
        for (int mt = 0; mt < 2; mt++) {
            float c[2][8][4];
            #pragma unroll
            for (int mb = 0; mb < 2; mb++)
                #pragma unroll
                for (int nb = 0; nb < 8; nb++)
                    #pragma unroll
                    for (int q = 0; q < 4; q++) c[mb][nb][q] = 0.f;

            #pragma unroll 1
            for (int kc = 0; kc < 2; kc++) {
                // ---- stage A (W rows) and B (x cols), this K-chunk ----
                {
                    int rg = mt * 128 + r2;
                    bool va = (rg < G3);
                    const float4* srcA = (const float4*)(W_ih + (long)rg * Fn
                                                         + kc * 64 + kh * 32);
                    const float4* srcB = (const float4*)(x + (long)(b0 + bcol) * sbt
                                                         + (long)(t0 + tcol) * Fn
                                                         + kc * 64 + kh * 32);
                    #pragma unroll
                    for (int i = 0; i < 8; i++) {
                        int off = r2 * KPITCH + (kh * 32 + 4 * i) * 2;
                        float4 va4 = va ? srcA[i] : make_float4(0.f, 0.f, 0.f, 0.f);
                        cvt8(sm + SM_AHI, sm + SM_ALO, off, va4);
                        cvt8(sm + SM_BHI, sm + SM_BLO, off, srcB[i]);
                    }
                }
                __syncthreads();

                // ---- mma, interleaved hi/lo passes: 4 ksteps of 16 ----
                #pragma unroll 1
                for (int ks = 0; ks < 4; ks++) {
                    const int kb = ks * 32;
                    uint32_t ahi[2][4], alo[2][4];
                    ldx4(ahi[0], smb + SM_AHI + aoff[0] + kb);
                    ldx4(ahi[1], smb + SM_AHI + aoff[1] + kb);
                    ldx4(alo[0], smb + SM_ALO + aoff[0] + kb);
                    ldx4(alo[1], smb + SM_ALO + aoff[1] + kb);
                    #pragma unroll
                    for (int nh = 0; nh < 2; nh++) {
                        uint32_t bh[4][2], bl[4][2];
                        #pragma unroll
                        for (int g = 0; g < 2; g++) {
                            uint32_t r4[4];
                            ldx4(r4, smb + SM_BHI + boff[nh][g] + kb);
                            bh[2*g][0] = r4[0]; bh[2*g][1] = r4[1];
                            bh[2*g+1][0] = r4[2]; bh[2*g+1][1] = r4[3];
                            ldx4(r4, smb + SM_BLO + boff[nh][g] + kb);
                            bl[2*g][0] = r4[0]; bl[2*g][1] = r4[1];
                            bl[2*g+1][0] = r4[2]; bl[2*g+1][1] = r4[3];
                        }
                        #pragma unroll
                        for (int mb = 0; mb < 2; mb++)
                            #pragma unroll
                            for (int j = 0; j < 4; j++) {
                                float* cc = c[mb][nh * 4 + j];
                                mma16816(cc, ahi[mb], bh[j]);
                                mma16816(cc, alo[mb], bh[j]);
                                mma16816(cc, ahi[mb], bl[j]);
                            }
                    }
                }
                __syncthreads();   // tiles free for restage / Cs overwrite
            }

            // ---- epilogue: transpose via smem, coalesced store + bias ----
            float* Cs = (float*)sm;
            {
                int lr = lane >> 2;
                int lc = (lane & 3) * 2;
                #pragma unroll
                for (int mb = 0; mb < 2; mb++) {
                    int row = wm + 16 * mb + lr;
                    #pragma unroll
                    for (int nb = 0; nb < 8; nb++) {
                        int col = wn + 8 * nb + lc;
                        Cs[col * CPITCH + row]           = c[mb][nb][0];
                        Cs[(col + 1) * CPITCH + row]     = c[mb][nb][1];
                        Cs[col * CPITCH + row + 8]       = c[mb][nb][2];
                        Cs[(col + 1) * CPITCH + row + 8] = c[mb][nb][3];
                    }
                }
                if (tid < 128) {
                    int rg = mt * 128 + tid;
                    bsm[tid] = (rg < G3) ? b_ih[rg] : 0.f;
                }
            }
            __syncthreads();
            {
                float* gxf = (float*)g_xg;
                int n  = tid >> 1;
                int rh = tid & 1;
                int tl = n >> 2, b = n & 3;
                long gbase = ((long)(t0 + tl) * NCTA + ctab) * 976 + b * 244 + mt * 128;
                int i0 = rh * 16;
                int i1 = rh ? ((mt == 0) ? 32 : 29) : 16;
                for (int i = i0; i < i1; i++) {
                    float4 cv = *(float4*)(Cs + n * CPITCH + 4 * i);
                    float4 bv = *(float4*)(bsm + 4 * i);
                    cv.x += bv.x; cv.y += bv.y; cv.z += bv.z; cv.w += bv.w;
                    *(float4*)(gxf + gbase + 4 * i) = cv;
                }
            }
            __syncthreads();   // stores done before Cs region restaged
        }
        // publish chunk
        if (tid == 0) {
            __threadfence();
            st_rel(&g_prog[ctab], (unsigned)(t0 + 32));
        }
    }
}

// =====================================================================
// Recurrence consumer role (R8-proven shape + chunk waits).
// =====================================================================
static __device__ void rec_role(char* sm, int ctab,
                                const float* __restrict__ W_hh,
                                const float* __restrict__ b_hh,
                                const float* __restrict__ fc_w,
                                const float* __restrict__ fc_b) {
    float4* hs4 = (float4*)(sm);               // 84
    float4* hg4 = (float4*)(sm + 1344);        // 244
    float4* xgs = (float4*)(sm + 5248);        // 2*244

    const int tid  = threadIdx.x;
    const int lane = tid & 31;
    const int warp = tid >> 5;

    const int p     = warp * 16 + (lane >> 1);
    const int kh    = lane & 1;
    const int kbase = kh * 41;
    const int r0 = 2 * p, r1 = 2 * p + 1;

    float wr0[41], wr1[41];
    #pragma unroll
    for (int i = 0; i < 41; i++) {
        int k = kbase + i;
        bool kok = (k < Hn);
        wr0[i] = (kok && r0 < G3) ? W_hh[r0 * Hn + k] : 0.f;
        wr1[i] = (kok && r1 < G3) ? W_hh[r1 * Hn + k] : 0.f;
    }
    const float bh0 = (r0 < G3) ? b_hh[r0] : 0.f;
    const float bh1 = (r1 < G3) ? b_hh[r1] : 0.f;

    if (tid < 84) hs4[tid] = make_float4(0.f, 0.f, 0.f, 0.f);

    // wait for chunk 0 (t = 0..31)
    if (tid == 0) { while (ld_acq(&g_prog[ctab]) < 32u) __nanosleep(128); }
    __syncthreads();

    if (tid < RPAD) xgs[tid] = g_xg[(long)ctab * RPAD + tid];
    __syncthreads();

    float* hs_f = (float*)hs4;

    for (int t = 0; t < Tn; t++) {
        const int cur = t & 1, nxt = cur ^ 1;
        const int u = t + 1;

        // chunk gate (32x per run)
        if (u < Tn && (u & 31) == 0) {
            if (tid == 0) {
                unsigned tgt = (unsigned)(u + 32);
                while (ld_acq(&g_prog[ctab]) < tgt) __nanosleep(128);
            }
            __syncthreads();
        }

        float4 q = make_float4(0.f, 0.f, 0.f, 0.f);
        const bool pf = (u < Tn);
        if (pf && tid < RPAD)
            q = g_xg[((long)u * NCTA + ctab) * RPAD + tid];

        unsigned long long c00 = 0, c01 = 0, c10 = 0, c11 = 0;
        const ulonglong2* hp = (const ulonglong2*)hs4;
        #pragma unroll
        for (int i = 0; i < 41; i++) {
            ulonglong2 hv = hp[kbase + i];
            unsigned long long w0 = dup2(wr0[i]);
            unsigned long long w1 = dup2(wr1[i]);
            ffma2(c00, w0, hv.x); ffma2(c01, w0, hv.y);
            ffma2(c10, w1, hv.x); ffma2(c11, w1, hv.y);
        }
        c00 = addx2(c00, __shfl_xor_sync(0xffffffffu, c00, 1));
        c01 = addx2(c01, __shfl_xor_sync(0xffffffffu, c01, 1));
        c10 = addx2(c10, __shfl_xor_sync(0xffffffffu, c10, 1));
        c11 = addx2(c11, __shfl_xor_sync(0xffffffffu, c11, 1));

        if (kh == 0 && p < NPAIR) {
            float2 u0 = unpk(c00), u1 = unpk(c01), u2 = unpk(c10), u3 = unpk(c11);
            hg4[r0] = make_float4(u0.x + bh0, u0.y + bh0, u1.x + bh0, u1.y + bh0);
            hg4[r1] = make_float4(u2.x + bh1, u2.y + bh1, u3.x + bh1, u3.y + bh1);
        }
        if (pf && tid < RPAD) xgs[nxt * RPAD + tid] = q;
        __syncthreads();

        const float* xgc = (const float*)(xgs + cur * RPAD);
        const float* hgf = (const float*)hg4;
        #pragma unroll
        for (int rep = 0; rep < 2; rep++) {
            int it = tid + rep * 256;
            if (it < Hn * 4) {
                int r = it >> 2, b = it & 3;
                float xr = xgc[b * RPAD + r];
                float xz = xgc[b * RPAD + Hn + r];
                float xn = xgc[b * RPAD + 2 * Hn + r];
                float hr = hgf[it];
                float hz = hgf[Hn * 4 + it];
                float hn = hgf[2 * Hn * 4 + it];
                float rr = sigm(xr + hr);
                float z  = sigm(xz + hz);
                float n  = tanh_f(xn + rr * hn);
                hs_f[it] = (1.f - z) * n + z * hs_f[it];
            }
        }
        __syncthreads();
    }

    if (tid < 32) {
        int b = tid >> 3, f = tid & 7;
        float a = fc_b[f];
        #pragma unroll 27
        for (int j = 0; j < Hn; j++) a += hs_f[j * 4 + b] * fc_w[f * Hn + j];
        a = a * sigm(a);
        g_h8[(ctab * BPC + b) * 8 + f] = a;
    }
}

// =====================================================================
// Fused kernel: 256 CTAs (128 producers + 128 consumers), all resident.
// =====================================================================
__global__ void __launch_bounds__(256, 2) fused_gru(
    const float* __restrict__ x,
    const float* __restrict__ W_ih,
    const float* __restrict__ b_ih,
    const float* __restrict__ W_hh,
    const float* __restrict__ b_hh,
    const float* __restrict__ fc_w,
    const float* __restrict__ fc_b)
{
    extern __shared__ char sm[];
    if (blockIdx.x < NCTA)
        gemm_role(sm, blockIdx.x, x, W_ih, b_ih);
    else
        rec_role(sm, blockIdx.x - NCTA, W_hh, b_hh, fc_w, fc_b);
}

// =====================================================================
// Head: BN(8) -> fc1 -> silu -> BN(4) -> fc2. One CTA, 512 threads.
// =====================================================================
__global__ void __launch_bounds__(Bn) head_kernel(
    const float* __restrict__ g1, const float* __restrict__ beta1,
    const float* __restrict__ fc1_w, const float* __restrict__ fc1_b,
    const float* __restrict__ g2, const float* __restrict__ beta2,
    const float* __restrict__ fc2_w, const float* __restrict__ fc2_b,
    float* __restrict__ out)
{
    __shared__ float s8[Bn * 8];
    __shared__ float s4[Bn * 4];
    __shared__ float mu1[8], iv1[8], mu2[4], iv2[4];
    const int tid = threadIdx.x;

    for (int i = tid; i < Bn * 8; i += Bn) s8[i] = g_h8[i];
    __syncthreads();

    if (tid < 8) {
        float s = 0.f, ss = 0.f;
        for (int b = 0; b < Bn; b++) { float v = s8[b * 8 + tid]; s += v; ss += v * v; }
        float m = s * (1.f / Bn);
        float var = ss * (1.f / Bn) - m * m;
        mu1[tid] = m;
        iv1[tid] = rsqrtf(var + 1e-5f);
    }
    __syncthreads();

    {
        int b = tid;
        float y[8];
        #pragma unroll
        for (int f = 0; f < 8; f++)
            y[f] = (s8[b * 8 + f] - mu1[f]) * iv1[f] * g1[f] + beta1[f];
        #pragma unroll
        for (int o = 0; o < 4; o++) {
            float a = fc1_b[o];
            #pragma unroll
            for (int f = 0; f < 8; f++) a += y[f] * fc1_w[o * 8 + f];
            a = a * sigm(a);
            s4[b * 4 + o] = a;
        }
    }
    __syncthreads();

    if (tid < 4) {
        float s = 0.f, ss = 0.f;
        for (int b = 0; b < Bn; b++) { float v = s4[b * 4 + tid]; s += v; ss += v * v; }
        float m = s * (1.f / Bn);
        float var = ss * (1.f / Bn) - m * m;
        mu2[tid] = m;
        iv2[tid] = rsqrtf(var + 1e-5f);
    }
    __syncthreads();

    {
        int b = tid;
        float a = fc2_b[0];
        #pragma unroll
        for (int o = 0; o < 4; o++)
            a += ((s4[b * 4 + o] - mu2[o]) * iv2[o] * g2[o] + beta2[o]) * fc2_w[o];
        out[b] = a;
    }
}

// =====================================================================
extern "C" void kernel_launch(void* const* d_in, const int* in_sizes, int n_in,
                              void* d_out, int out_size) {
    const float* x     = (const float*)d_in[0];
    const float* W_ih  = (const float*)d_in[1];
    const float* W_hh  = (const float*)d_in[2];
    const float* b_ih  = (const float*)d_in[3];
    const float* b_hh  = (const float*)d_in[4];
    const float* fc_w  = (const float*)d_in[5];
    const float* fc_b  = (const float*)d_in[6];
    const float* g1    = (const float*)d_in[7];
    const float* beta1 = (const float*)d_in[8];
    const float* fc1_w = (const float*)d_in[9];
    const float* fc1_b = (const float*)d_in[10];
    const float* g2    = (const float*)d_in[11];
    const float* beta2 = (const float*)d_in[12];
    const float* fc2_w = (const float*)d_in[13];
    const float* fc2_b = (const float*)d_in[14];
    float* out = (float*)d_out;

    cudaFuncSetAttribute(fused_gru, cudaFuncAttributeMaxDynamicSharedMemorySize, SM_BYTES);

    fused_gru<<<2 * NCTA, 256, SM_BYTES>>>(x, W_ih, b_ih, W_hh, b_hh, fc_w, fc_b);
    head_kernel<<<1, Bn>>>(g1, beta1, fc1_w, fc1_b, g2, beta2, fc2_w, fc2_b, out);
}

// round 10
// speedup vs baseline: 1.0276x; 1.0276x over previous
#include <cuda_runtime.h>
#include <cuda_bf16.h>
#include <cstdint>
#include <math.h>

// Problem constants
#define Hn    81
#define G3    243          // 3*H
#define RPAD  244
#define NPAIR 122
#define Fn    128
#define Tn    1024
#define Bn    512
#define BPC   4
#define NCTA  128          // 512/4

// =====================================================================
// Device scratch: XG[t][ctab][b(4)][r(244)] floats = 512 MB
// =====================================================================
__device__ float4 g_xg[Tn * NCTA * RPAD];
__device__ float g_h8[Bn * 8];

// ---------- packed f32x2 helpers ----------
static __device__ __forceinline__ unsigned long long dup2(float x) {
    unsigned long long r;
    asm("mov.b64 %0, {%1, %1};" : "=l"(r) : "f"(x));
    return r;
}
static __device__ __forceinline__ void ffma2(unsigned long long &d,
                                             unsigned long long a,
                                             unsigned long long b) {
    asm("fma.rn.f32x2 %0, %1, %2, %0;" : "+l"(d) : "l"(a), "l"(b));
}
static __device__ __forceinline__ unsigned long long addx2(unsigned long long a,
                                                           unsigned long long b) {
    unsigned long long r;
    asm("add.rn.f32x2 %0, %1, %2;" : "=l"(r) : "l"(a), "l"(b));
    return r;
}
static __device__ __forceinline__ float2 unpk(unsigned long long v) {
    float lo, hi;
    asm("mov.b64 {%0, %1}, %2;" : "=f"(lo), "=f"(hi) : "l"(v));
    return make_float2(lo, hi);
}

// ---------- fast activations ----------
static __device__ __forceinline__ float sigm(float x) {
    x = fminf(fmaxf(x, -30.f), 30.f);
    return __fdividef(1.f, 1.f + __expf(-x));
}
static __device__ __forceinline__ float tanh_f(float x) {
    x = fminf(fmaxf(x, -20.f), 20.f);
    float e = __expf(-2.f * x);
    return __fdividef(1.f - e, 1.f + e);
}

// =====================================================================
// Kernel 1: XG = x @ W_ih^T + b_ih via mma.sync bf16 (R8 winner, verbatim).
// =====================================================================
#define PITCH    272
#define TILE_SZ  (128 * PITCH)
#define SM_AHI   0
#define SM_ALO   (SM_AHI + TILE_SZ)
#define SM_BHI   (SM_ALO + TILE_SZ)
#define SM_BLO   (SM_BHI + TILE_SZ)
#define SM_BS    (4 * TILE_SZ)
#define SM_MMA_BYTES (SM_BS + 512)
#define CPITCH   132

static __device__ __forceinline__ uint32_t smem_u32(const void* p) {
    uint32_t a;
    asm("{ .reg .u64 t; cvta.to.shared.u64 t, %1; cvt.u32.u64 %0, t; }"
        : "=r"(a) : "l"(p));
    return a;
}
static __device__ __forceinline__ uint32_t bfpack(float a, float b) {
    uint32_t r;
    asm("cvt.rn.bf16x2.f32 %0, %1, %2;" : "=r"(r) : "f"(b), "f"(a));
    return r;
}
static __device__ __forceinline__ void cvt8(char* thi, char* tlo, int off, float4 v) {
    uint32_t h0 = bfpack(v.x, v.y);
    uint32_t h1 = bfpack(v.z, v.w);
    float fx = __uint_as_float(h0 << 16);
    float fy = __uint_as_float(h0 & 0xffff0000u);
    float fz = __uint_as_float(h1 << 16);
    float fw = __uint_as_float(h1 & 0xffff0000u);
    uint32_t l0 = bfpack(v.x - fx, v.y - fy);
    uint32_t l1 = bfpack(v.z - fz, v.w - fw);
    *(uint2*)(thi + off) = make_uint2(h0, h1);
    *(uint2*)(tlo + off) = make_uint2(l0, l1);
}
static __device__ __forceinline__ void ldx4(uint32_t* r, uint32_t addr) {
    asm volatile("ldmatrix.sync.aligned.m8n8.x4.shared.b16 {%0,%1,%2,%3}, [%4];"
                 : "=r"(r[0]), "=r"(r[1]), "=r"(r[2]), "=r"(r[3]) : "r"(addr));
}
static __device__ __forceinline__ void mma16816(float* c, const uint32_t* a,
                                                const uint32_t* b) {
    asm volatile(
        "mma.sync.aligned.m16n8k16.row.col.f32.bf16.bf16.f32 "
        "{%0,%1,%2,%3}, {%4,%5,%6,%7}, {%8,%9}, {%0,%1,%2,%3};"
        : "+f"(c[0]), "+f"(c[1]), "+f"(c[2]), "+f"(c[3])
        : "r"(a[0]), "r"(a[1]), "r"(a[2]), "r"(a[3]), "r"(b[0]), "r"(b[1]));
}

__global__ void __launch_bounds__(256, 1) xg_mma(
    const float* __restrict__ x,
    const float* __restrict__ W_ih,
    const float* __restrict__ b_ih)
{
    extern __shared__ char sm[];
    const uint32_t smb = smem_u32(sm);
    float* bsm = (float*)(sm + SM_BS);

    const int tid  = threadIdx.x;
    const int lane = tid & 31;
    const int w    = tid >> 5;
    const int ctab = blockIdx.x;
    const int b0   = ctab * BPC;
    const int t0   = blockIdx.y * 32;
    const int mt   = blockIdx.z;
    const long sbt = (long)Tn * Fn;

    {
        const int r2 = tid >> 1;
        const int kh = tid & 1;
        {
            int rg = mt * 128 + r2;
            char* thi = sm + SM_AHI;
            char* tlo = sm + SM_ALO;
            const float4* src = (const float4*)(W_ih + (long)rg * Fn);
            bool valid = (rg < G3);
            #pragma unroll
            for (int i = 0; i < 16; i++) {
                int k = kh * 64 + i * 4;
                float4 v = valid ? src[k >> 2] : make_float4(0.f, 0.f, 0.f, 0.f);
                cvt8(thi, tlo, r2 * PITCH + k * 2, v);
            }
        }
        {
            int b = r2 & 3, tl = r2 >> 2;
            char* thi = sm + SM_BHI;
            char* tlo = sm + SM_BLO;
            const float4* src = (const float4*)(x + (long)(b0 + b) * sbt
                                                + (long)(t0 + tl) * Fn);
            #pragma unroll
            for (int i = 0; i < 16; i++) {
                int k = kh * 64 + i * 4;
                cvt8(thi, tlo, r2 * PITCH + k * 2, src[k >> 2]);
            }
        }
        if (tid < 128) {
            int rg = mt * 128 + tid;
            bsm[tid] = (rg < G3) ? b_ih[rg] : 0.f;
        }
    }
    __syncthreads();

    const int wm = (w & 3) * 32;
    const int wn = (w >> 2) * 64;

    float c[2][8][4];
    #pragma unroll
    for (int mb = 0; mb < 2; mb++)
        #pragma unroll
        for (int nb = 0; nb < 8; nb++)
            #pragma unroll
            for (int q = 0; q < 4; q++) c[mb][nb][q] = 0.f;

    int aoff[2], boff[4];
    {
        int lr = lane & 15, lk8 = (lane >> 4) * 8;
        aoff[0] = (wm + lr) * PITCH + lk8 * 2;
        aoff[1] = (wm + 16 + lr) * PITCH + lk8 * 2;
        int sel = lane >> 3;
        int nrow = wn + (lane & 7) + (sel >> 1) * 8;
        int kk = (sel & 1) * 8;
        #pragma unroll
        for (int g = 0; g < 4; g++)
            boff[g] = (nrow + 16 * g) * PITCH + kk * 2;
    }

    const uint32_t abase[3] = { smb + SM_AHI, smb + SM_ALO, smb + SM_AHI };
    const uint32_t bbase[3] = { smb + SM_BHI, smb + SM_BHI, smb + SM_BLO };

    #pragma unroll 1
    for (int pass = 0; pass < 3; pass++) {
        const uint32_t Ab = abase[pass], Bb = bbase[pass];
        #pragma unroll 1
        for (int ks = 0; ks < 8; ks++) {
            const int kb = ks * 32;
            uint32_t a[2][4], bb[8][2];
            ldx4(a[0], Ab + aoff[0] + kb);
            ldx4(a[1], Ab + aoff[1] + kb);
            #pragma unroll
            for (int g = 0; g < 4; g++) {
                uint32_t r4[4];
                ldx4(r4, Bb + boff[g] + kb);
                bb[2 * g][0] = r4[0]; bb[2 * g][1] = r4[1];
                bb[2 * g + 1][0] = r4[2]; bb[2 * g + 1][1] = r4[3];
            }
            #pragma unroll
            for (int mb = 0; mb < 2; mb++)
                #pragma unroll
                for (int nb = 0; nb < 8; nb++)
                    mma16816(c[mb][nb], a[mb], bb[nb]);
        }
    }

    __syncthreads();
    float* Cs = (float*)sm;
    {
        int lr = lane >> 2;
        int lc = (lane & 3) * 2;
        #pragma unroll
        for (int mb = 0; mb < 2; mb++) {
            int row = wm + 16 * mb + lr;
            #pragma unroll
            for (int nb = 0; nb < 8; nb++) {
                int col = wn + 8 * nb + lc;
                Cs[col * CPITCH + row]           = c[mb][nb][0];
                Cs[(col + 1) * CPITCH + row]     = c[mb][nb][1];
                Cs[col * CPITCH + row + 8]       = c[mb][nb][2];
                Cs[(col + 1) * CPITCH + row + 8] = c[mb][nb][3];
            }
        }
    }
    __syncthreads();
    {
        float* gxf = (float*)g_xg;
        int n  = tid >> 1;
        int rh = tid & 1;
        int tl = n >> 2, b = n & 3;
        long gbase = ((long)(t0 + tl) * NCTA + ctab) * 976 + b * 244 + mt * 128;
        int i0 = rh * 16;
        int i1 = rh ? ((mt == 0) ? 32 : 29) : 16;
        for (int i = i0; i < i1; i++) {
            float4 cv = *(float4*)(Cs + n * CPITCH + 4 * i);
            float4 bv = *(float4*)(bsm + 4 * i);
            cv.x += bv.x; cv.y += bv.y; cv.z += bv.z; cv.w += bv.w;
            *(float4*)(gxf + gbase + 4 * i) = cv;
        }
    }
}

// =====================================================================
// Kernel 2: recurrence v4. 256 CTAs x 2 batches x 256 threads, 2 CTAs/SM.
// Same pair/k-half scheme as R8, but f32x2 packs the CTA's 2 batches.
// =====================================================================
__global__ void __launch_bounds__(256, 2) gru_rec2(
    const float* __restrict__ W_hh,  // [3H,H]
    const float* __restrict__ b_hh,  // [3H]
    const float* __restrict__ fc_w,  // [8,H]
    const float* __restrict__ fc_b)  // [8]
{
    __shared__ float2 hs2[84];          // h[j] for 2 batches
    __shared__ float2 hg2[RPAD];        // hidden gates [r] x 2 batches
    __shared__ float4 xgs[2 * 122];     // double-buffered xg chunk (488 floats)

    const int tid  = threadIdx.x;
    const int lane = tid & 31;
    const int warp = tid >> 5;
    const int c2   = blockIdx.x;        // 0..255
    const int ctab = c2 >> 1;
    const int bh2  = c2 & 1;            // batch pair within ctab group

    const int p     = warp * 16 + (lane >> 1);   // pair 0..127 (valid < 122)
    const int kh    = lane & 1;
    const int kbase = kh * 41;
    const int r0 = 2 * p, r1 = 2 * p + 1;

    float wr0[41], wr1[41];
    #pragma unroll
    for (int i = 0; i < 41; i++) {
        int k = kbase + i;
        bool kok = (k < Hn);
        wr0[i] = (kok && r0 < G3) ? W_hh[r0 * Hn + k] : 0.f;
        wr1[i] = (kok && r1 < G3) ? W_hh[r1 * Hn + k] : 0.f;
    }
    const float bh0 = (r0 < G3) ? b_hh[r0] : 0.f;
    const float bh1 = (r1 < G3) ? b_hh[r1] : 0.f;

    if (tid < 84) hs2[tid] = make_float2(0.f, 0.f);
    if (tid < 122) xgs[tid] = g_xg[(long)ctab * RPAD + bh2 * 122 + tid];  // t=0
    __syncthreads();

    float* hs_f = (float*)hs2;

    for (int t = 0; t < Tn; t++) {
        const int cur = t & 1, nxt = cur ^ 1;

        float4 q = make_float4(0.f, 0.f, 0.f, 0.f);
        const bool pf = (t + 1 < Tn);
        if (pf && tid < 122)
            q = g_xg[((long)(t + 1) * NCTA + ctab) * RPAD + bh2 * 122 + tid];

        // hg partial over this lane's k-half: 2 rows x 2 batches (f32x2)
        unsigned long long c0 = 0, c1 = 0;
        const unsigned long long* hp = (const unsigned long long*)hs2;
        #pragma unroll
        for (int i = 0; i < 41; i++) {
            unsigned long long hv = hp[kbase + i];
            ffma2(c0, dup2(wr0[i]), hv);
            ffma2(c1, dup2(wr1[i]), hv);
        }
        c0 = addx2(c0, __shfl_xor_sync(0xffffffffu, c0, 1));
        c1 = addx2(c1, __shfl_xor_sync(0xffffffffu, c1, 1));

        if (kh == 0 && p < NPAIR) {
            float2 u0 = unpk(c0), u1 = unpk(c1);
            hg2[r0] = make_float2(u0.x + bh0, u0.y + bh0);
            hg2[r1] = make_float2(u1.x + bh1, u1.y + bh1);
        }
        if (pf && tid < 122) xgs[nxt * 122 + tid] = q;
        __syncthreads();

        // gate combine: 81 hidden x 2 batches = 162 items, single round
        if (tid < Hn * 2) {
            int r = tid >> 1, b = tid & 1;
            const float* xgc = (const float*)(xgs + cur * 122);  // [b][g*81+r]
            const float* hgf = (const float*)hg2;
            float xr = xgc[b * 244 + r];
            float xz = xgc[b * 244 + Hn + r];
            float xn = xgc[b * 244 + 2 * Hn + r];
            float hr = hgf[r * 2 + b];
            float hz = hgf[(Hn + r) * 2 + b];
            float hn = hgf[(2 * Hn + r) * 2 + b];
            float rr = sigm(xr + hr);
            float z  = sigm(xz + hz);
            float n  = tanh_f(xn + rr * hn);
            hs_f[r * 2 + b] = (1.f - z) * n + z * hs_f[r * 2 + b];
        }
        __syncthreads();
    }

    // head stage 1 for this CTA's 2 batches
    if (tid < 16) {
        int b = tid >> 3, f = tid & 7;
        float a = fc_b[f];
        #pragma unroll 27
        for (int j = 0; j < Hn; j++) a += hs_f[j * 2 + b] * fc_w[f * Hn + j];
        a = a * sigm(a);
        g_h8[(ctab * BPC + bh2 * 2 + b) * 8 + f] = a;
    }
}

// =====================================================================
// Kernel 3: BN(8) -> fc1 -> silu -> BN(4) -> fc2. One CTA, 512 threads.
// =====================================================================
__global__ void __launch_bounds__(Bn) head_kernel(
    const float* __restrict__ g1, const float* __restrict__ beta1,
    const float* __restrict__ fc1_w, const float* __restrict__ fc1_b,
    const float* __restrict__ g2, const float* __restrict__ beta2,
    const float* __restrict__ fc2_w, const float* __restrict__ fc2_b,
    float* __restrict__ out)
{
    __shared__ float s8[Bn * 8];
    __shared__ float s4[Bn * 4];
    __shared__ float mu1[8], iv1[8], mu2[4], iv2[4];
    const int tid = threadIdx.x;

    for (int i = tid; i < Bn * 8; i += Bn) s8[i] = g_h8[i];
    __syncthreads();

    if (tid < 8) {
        float s = 0.f, ss = 0.f;
        for (int b = 0; b < Bn; b++) { float v = s8[b * 8 + tid]; s += v; ss += v * v; }
        float m = s * (1.f / Bn);
        float var = ss * (1.f / Bn) - m * m;
        mu1[tid] = m;
        iv1[tid] = rsqrtf(var + 1e-5f);
    }
    __syncthreads();

    {
        int b = tid;
        float y[8];
        #pragma unroll
        for (int f = 0; f < 8; f++)
            y[f] = (s8[b * 8 + f] - mu1[f]) * iv1[f] * g1[f] + beta1[f];
        #pragma unroll
        for (int o = 0; o < 4; o++) {
            float a = fc1_b[o];
            #pragma unroll
            for (int f = 0; f < 8; f++) a += y[f] * fc1_w[o * 8 + f];
            a = a * sigm(a);
            s4[b * 4 + o] = a;
        }
    }
    __syncthreads();

    if (tid < 4) {
        float s = 0.f, ss = 0.f;
        for (int b = 0; b < Bn; b++) { float v = s4[b * 4 + tid]; s += v; ss += v * v; }
        float m = s * (1.f / Bn);
        float var = ss * (1.f / Bn) - m * m;
        mu2[tid] = m;
        iv2[tid] = rsqrtf(var + 1e-5f);
    }
    __syncthreads();

    {
        int b = tid;
        float a = fc2_b[0];
        #pragma unroll
        for (int o = 0; o < 4; o++)
            a += ((s4[b * 4 + o] - mu2[o]) * iv2[o] * g2[o] + beta2[o]) * fc2_w[o];
        out[b] = a;
    }
}

// =====================================================================
extern "C" void kernel_launch(void* const* d_in, const int* in_sizes, int n_in,
                              void* d_out, int out_size) {
    const float* x     = (const float*)d_in[0];
    const float* W_ih  = (const float*)d_in[1];
    const float* W_hh  = (const float*)d_in[2];
    const float* b_ih  = (const float*)d_in[3];
    const float* b_hh  = (const float*)d_in[4];
    const float* fc_w  = (const float*)d_in[5];
    const float* fc_b  = (const float*)d_in[6];
    const float* g1    = (const float*)d_in[7];
    const float* beta1 = (const float*)d_in[8];
    const float* fc1_w = (const float*)d_in[9];
    const float* fc1_b = (const float*)d_in[10];
    const float* g2    = (const float*)d_in[11];
    const float* beta2 = (const float*)d_in[12];
    const float* fc2_w = (const float*)d_in[13];
    const float* fc2_b = (const float*)d_in[14];
    float* out = (float*)d_out;

    cudaFuncSetAttribute(xg_mma, cudaFuncAttributeMaxDynamicSharedMemorySize, SM_MMA_BYTES);

    xg_mma<<<dim3(NCTA, 32, 2), 256, SM_MMA_BYTES>>>(x, W_ih, b_ih);
    gru_rec2<<<2 * NCTA, 256>>>(W_hh, b_hh, fc_w, fc_b);
    head_kernel<<<1, Bn>>>(g1, beta1, fc1_w, fc1_b, g2, beta2, fc2_w, fc2_b, out);
}